// round 4
// baseline (speedup 1.0000x reference)
#include <cuda_runtime.h>

#define NTHREADS 256
#define MAX_BLOCKS 8192

#define C_PER_SAMPLE 7.1624450756f  // prior+lik constants per sample
#define C_ENTROPY    5.6757541328f  // 0.5*4*(1+log 2pi)

// ---------------- packed f32x2 helpers ----------------
union F2 { float2 f; unsigned long long u; };
union F4 { float4 v; F2 h[2]; };

__device__ __forceinline__ F2 mk2(float a, float b) { F2 r; r.f.x = a; r.f.y = b; return r; }
__device__ __forceinline__ F2 fma2(F2 a, F2 b, F2 c) {
    F2 d; asm("fma.rn.f32x2 %0, %1, %2, %3;" : "=l"(d.u) : "l"(a.u), "l"(b.u), "l"(c.u)); return d;
}
__device__ __forceinline__ F2 add2(F2 a, F2 b) {
    F2 d; asm("add.rn.f32x2 %0, %1, %2;" : "=l"(d.u) : "l"(a.u), "l"(b.u)); return d;
}
__device__ __forceinline__ F2 mul2(F2 a, F2 b) {
    F2 d; asm("mul.rn.f32x2 %0, %1, %2;" : "=l"(d.u) : "l"(a.u), "l"(b.u)); return d;
}
__device__ __forceinline__ F2 relu2(F2 a) {
    F2 r; r.f.x = fmaxf(a.f.x, 0.0f); r.f.y = fmaxf(a.f.y, 0.0f); return r;
}

// ---------------- weight layouts ----------------
// Row-pair scheme: every weight operand is a duplicated pair {w,w}.
// A float4 carries two consecutive duplicated weights.
struct WConst {                 // layers 1 & 3 -> constant port (LDC)
    float4 l1w0[3][10];         // {W1[0][2jp]x2, W1[0][2jp+1]x2}
    float4 l1w1[3][10];
    float4 l1b [3][10];
    float4 w3  [3][6][5];       // {W3[2kq][o]x2, W3[2kq+1][o]x2}
    float2 b3d [3][6];          // {b,b}
};
struct WGlob {                  // layer 2 -> L1tex (broadcast LDG)
    float4 w2 [3][10][10];      // {W2[2jq][k]x2, W2[2jq+1][k]x2}
    float2 b2d[3][10];
};

__constant__ WConst c_w;
__device__   WConst g_cstage;
__device__   WGlob  g_w2;
__device__ double g_partial[MAX_BLOCKS];
__device__ unsigned int g_ticket;

// ---------------------------------------------------------------------------
__global__ void pack_kernel(
    const float* mW1, const float* mb1, const float* mW2, const float* mb2,
    const float* mW3, const float* mb3,
    const float* dW1, const float* db1, const float* dW2, const float* db2,
    const float* dW3, const float* db3,
    const float* oW1, const float* ob1, const float* oW2, const float* ob2,
    const float* oW3, const float* ob3)
{
    const float* W1[3] = {mW1, dW1, oW1};
    const float* B1[3] = {mb1, db1, ob1};
    const float* W2[3] = {mW2, dW2, oW2};
    const float* B2[3] = {mb2, db2, ob2};
    const float* W3[3] = {mW3, dW3, oW3};
    const float* B3[3] = {mb3, db3, ob3};
    const int OUT[3] = {4, 4, 6};
    int t = threadIdx.x;

    for (int i = t; i < 30; i += blockDim.x) {           // layer1
        int m = i / 10, jp = i % 10, j = 2 * jp;
        float a0 = W1[m][j],      a1 = W1[m][j + 1];
        float b0 = W1[m][20 + j], b1 = W1[m][20 + j + 1];
        float c0 = B1[m][j],      c1 = B1[m][j + 1];
        g_cstage.l1w0[m][jp] = make_float4(a0, a0, a1, a1);
        g_cstage.l1w1[m][jp] = make_float4(b0, b0, b1, b1);
        g_cstage.l1b [m][jp] = make_float4(c0, c0, c1, c1);
    }
    for (int i = t; i < 300; i += blockDim.x) {          // layer2 (global)
        int m = i / 100, r = i % 100, k = r / 10, jq = r % 10, j = 2 * jq;
        float w0 = W2[m][j * 10 + k], w1 = W2[m][(j + 1) * 10 + k];
        g_w2.w2[m][k][jq] = make_float4(w0, w0, w1, w1);
    }
    for (int i = t; i < 30; i += blockDim.x) {
        int m = i / 10, k = i % 10;
        float b = B2[m][k];
        g_w2.b2d[m][k] = make_float2(b, b);
    }
    for (int i = t; i < 90; i += blockDim.x) {           // layer3
        int m = i / 30, r = i % 30, o = r / 5, kq = r % 5, k = 2 * kq;
        int Om = OUT[m];
        float w0 = (o < Om) ? W3[m][k * Om + o] : 0.0f;
        float w1 = (o < Om) ? W3[m][(k + 1) * Om + o] : 0.0f;
        g_cstage.w3[m][o][kq] = make_float4(w0, w0, w1, w1);
    }
    for (int i = t; i < 18; i += blockDim.x) {
        int m = i / 6, o = i % 6;
        float b = (o < OUT[m]) ? B3[m][o] : 0.0f;
        g_cstage.b3d[m][o] = make_float2(b, b);
    }
}

// ---------------------------------------------------------------------------
template <int M, int OUT>
__device__ __forceinline__ void mlp_eval2(F2 y0d, F2 y1d, F2* out)
{
    F2 h[20];
#pragma unroll
    for (int jp = 0; jp < 10; jp++) {
        F4 a, b, c;
        a.v = c_w.l1w0[M][jp];
        b.v = c_w.l1w1[M][jp];
        c.v = c_w.l1b [M][jp];
        h[2 * jp]     = relu2(fma2(a.h[0], y0d, fma2(b.h[0], y1d, c.h[0])));
        h[2 * jp + 1] = relu2(fma2(a.h[1], y0d, fma2(b.h[1], y1d, c.h[1])));
    }
    F2 h2[10];
#pragma unroll
    for (int k = 0; k < 10; k++) {
        F2 acc;
        acc.f = __ldg(&g_w2.b2d[M][k]);
#pragma unroll
        for (int jq = 0; jq < 10; jq++) {
            F4 w; w.v = __ldg(&g_w2.w2[M][k][jq]);
            acc = fma2(h[2 * jq], w.h[0], fma2(h[2 * jq + 1], w.h[1], acc));
        }
        h2[k] = relu2(acc);
    }
#pragma unroll
    for (int o = 0; o < OUT; o++) {
        F2 acc; acc.f = c_w.b3d[M][o];
#pragma unroll
        for (int kq = 0; kq < 5; kq++) {
            F4 w; w.v = c_w.w3[M][o][kq];
            acc = fma2(h2[2 * kq], w.h[0], fma2(h2[2 * kq + 1], w.h[1], acc));
        }
        out[o] = acc;
    }
}

__device__ __forceinline__ float softplus_f(float x)
{
    // cheap: max(x,0) + log(1 + exp(-|x|)); abs error ~1e-6, plenty for tol 1e-3
    return fmaxf(x, 0.0f) + __logf(1.0f + __expf(-fabsf(x)));
}

// ---------------------------------------------------------------------------
__global__ void __launch_bounds__(NTHREADS, 2)
vi_kernel(const float* __restrict__ y, const float* __restrict__ zs, int N,
          float* __restrict__ out)
{
    __shared__ double sred[NTHREADS];
    __shared__ float wsum[NTHREADS / 32];
    __shared__ int sh_last;

    int tid = threadIdx.x;
    int g = blockIdx.x * NTHREADS + tid;
    int n0 = 2 * g, n1 = n0 + 1;
    float val = 0.0f;

    if (n0 < N) {
        bool two = (n1 < N);
        float4 yv;
        if (two) {
            yv = ((const float4*)y)[g];
        } else {
            float2 ya = ((const float2*)y)[n0];
            yv = make_float4(ya.x, ya.y, ya.x, ya.y);
            n1 = n0;
        }
        F2 y0d = mk2(yv.x, yv.z);   // lane0 = row n0, lane1 = row n1
        F2 y1d = mk2(yv.y, yv.w);

        F2 mu[4], ldr[4], off[6];
        mlp_eval2<0, 4>(y0d, y1d, mu);
        mlp_eval2<1, 4>(y0d, y1d, ldr);
        mlp_eval2<2, 6>(y0d, y1d, off);

        F2 d0 = mk2(softplus_f(ldr[0].f.x), softplus_f(ldr[0].f.y));
        F2 d1 = mk2(softplus_f(ldr[1].f.x), softplus_f(ldr[1].f.y));
        F2 d2 = mk2(softplus_f(ldr[2].f.x), softplus_f(ldr[2].f.y));
        F2 d3 = mk2(softplus_f(ldr[3].f.x), softplus_f(ldr[3].f.y));

        const float4* zpA = (const float4*)zs + (size_t)n0 * 8;
        const float4* zpB = (const float4*)zs + (size_t)n1 * 8;

        F2 yx100 = mul2(y0d, mk2(100.0f, 100.0f));
        F2 yy100 = mul2(y1d, mk2(100.0f, 100.0f));
        const F2 m100 = mk2(-100.0f, -100.0f);

        float accA = 0.0f, accB = 0.0f;
#pragma unroll
        for (int p = 0; p < 8; p++) {
            float4 zA = __ldg(&zpA[p]);
            float4 zB = __ldg(&zpB[p]);
            F2 zx = mk2(zA.x, zB.x);
            F2 zy = mk2(zA.y, zB.y);
            F2 zz = mk2(zA.z, zB.z);
            F2 zw = mk2(zA.w, zB.w);

            F2 xi0 = fma2(d0, zx, mu[0]);
            F2 xi1 = fma2(d1, zy, fma2(off[0], zx, mu[1]));
            F2 xi2 = fma2(d2, zz, fma2(off[2], zy, fma2(off[1], zx, mu[2])));
            F2 xi3 = fma2(d3, zw, fma2(off[5], zz,
                          fma2(off[4], zy, fma2(off[3], zx, mu[3]))));

            F2 a2 = add2(xi1, xi2);
            F2 a3 = add2(a2, xi3);

            float s1a, c1a, s2a, c2a, s3a, c3a;
            float s1b, c1b, s2b, c2b, s3b, c3b;
            __sincosf(xi1.f.x, &s1a, &c1a);
            __sincosf(a2.f.x,  &s2a, &c2a);
            __sincosf(a3.f.x,  &s3a, &c3a);
            __sincosf(xi1.f.y, &s1b, &c1b);
            __sincosf(a2.f.y,  &s2b, &c2b);
            __sincosf(a3.f.y,  &s3b, &c3b);

            F2 px = mk2(fmaf(0.5f, c1a, fmaf(0.5f, c2a, c3a)),
                        fmaf(0.5f, c1b, fmaf(0.5f, c2b, c3b)));
            F2 py = mk2(xi0.f.x + fmaf(0.5f, s1a, fmaf(0.5f, s2a, s3a)),
                        xi0.f.y + fmaf(0.5f, s1b, fmaf(0.5f, s2b, s3b)));

            F2 rx = fma2(m100, px, yx100);
            F2 ry = fma2(m100, py, yy100);
            F2 r2 = fma2(rx, rx, mul2(ry, ry));

            F2 t0 = mul2(xi0, mk2(4.0f, 4.0f));
            F2 t1 = add2(xi1, xi1);
            F2 t2 = add2(xi2, xi2);
            F2 t3 = add2(xi3, xi3);
            F2 q  = fma2(t0, t0, fma2(t1, t1, fma2(t2, t2, mul2(t3, t3))));

            accA = fmaf(-0.5f, q.f.x + r2.f.x, accA);
            accB = fmaf(-0.5f, q.f.y + r2.f.y, accB);
        }

        float entA = __logf(d0.f.x * d1.f.x * d2.f.x * d3.f.x);
        float entB = __logf(d0.f.y * d1.f.y * d2.f.y * d3.f.y);
        float vA = fmaf(accA, 0.125f, C_PER_SAMPLE) + C_ENTROPY + entA;
        float vB = fmaf(accB, 0.125f, C_PER_SAMPLE) + C_ENTROPY + entB;
        val = two ? (vA + vB) : vA;
    }

    // ---- deterministic block reduction ----
#pragma unroll
    for (int o = 16; o > 0; o >>= 1)
        val += __shfl_down_sync(0xffffffffu, val, o);
    if ((tid & 31) == 0) wsum[tid >> 5] = val;
    __syncthreads();
    if (tid == 0) {
        double s = 0.0;
#pragma unroll
        for (int w = 0; w < NTHREADS / 32; w++) s += (double)wsum[w];
        g_partial[blockIdx.x] = s;
        __threadfence();
        unsigned t = atomicAdd(&g_ticket, 1u);
        sh_last = (t == gridDim.x - 1) ? 1 : 0;
    }
    __syncthreads();

    // ---- fused finalize: last block reduces partials deterministically ----
    if (sh_last) {
        __threadfence();
        double s = 0.0;
        for (int i = tid; i < (int)gridDim.x; i += NTHREADS)
            s += __ldcg(&g_partial[i]);
        sred[tid] = s;
        __syncthreads();
#pragma unroll
        for (int st = NTHREADS / 2; st > 0; st >>= 1) {
            if (tid < st) sred[tid] += sred[tid + st];
            __syncthreads();
        }
        if (tid == 0) {
            out[0] = (float)(sred[0] / (double)N);
            __threadfence();
            g_ticket = 0;   // reset for next graph replay
        }
    }
}

// ---------------------------------------------------------------------------
extern "C" void kernel_launch(void* const* d_in, const int* in_sizes, int n_in,
                              void* d_out, int out_size)
{
    const float* y  = (const float*)d_in[0];
    const float* zs = (const float*)d_in[1];
    int N = in_sizes[0] / 2;
    int npairs = (N + 1) / 2;
    int nblocks = (npairs + NTHREADS - 1) / NTHREADS;
    if (nblocks > MAX_BLOCKS) nblocks = MAX_BLOCKS;

    pack_kernel<<<1, 128>>>(
        (const float*)d_in[2],  (const float*)d_in[3],  (const float*)d_in[4],
        (const float*)d_in[5],  (const float*)d_in[6],  (const float*)d_in[7],
        (const float*)d_in[8],  (const float*)d_in[9],  (const float*)d_in[10],
        (const float*)d_in[11], (const float*)d_in[12], (const float*)d_in[13],
        (const float*)d_in[14], (const float*)d_in[15], (const float*)d_in[16],
        (const float*)d_in[17], (const float*)d_in[18], (const float*)d_in[19]);

    void* caddr = nullptr;
    void* saddr = nullptr;
    cudaGetSymbolAddress(&caddr, c_w);
    cudaGetSymbolAddress(&saddr, g_cstage);
    cudaMemcpyAsync(caddr, saddr, sizeof(WConst), cudaMemcpyDeviceToDevice, 0);

    vi_kernel<<<nblocks, NTHREADS>>>(y, zs, N, (float*)d_out);
}

// round 5
// speedup vs baseline: 1.4174x; 1.4174x over previous
#include <cuda_runtime.h>

#define NTHREADS 256
#define MAX_BLOCKS 8192

#define C_PER_SAMPLE 7.1624450756f  // prior+lik constants per sample
#define C_ENTROPY    5.6757541328f  // 0.5*4*(1+log 2pi)

// ---------------- weight layouts ----------------
// Constant port: layer-3 weights + all biases (small traffic, LDC floor ok).
struct WConst {
    float4 w3[3][6][3];   // w3[m][o][q] = W3[4q..4q+3][o]  (pad k>=10, o>=OUT -> 0)
    float  b2[3][10];
    float  b3[3][6];
};
// Shared-memory staging (via global): layer-1 + layer-2 weights.
struct SPack {
    float4 l1[3][20];     // (W1[0][j], W1[1][j], b1[j], 0)
    float4 w2[3][10][5];  // w2[m][k][q] = W2[4q..4q+3][k]
};

__constant__ WConst c_w;
__device__   WConst g_cstage;
__device__   SPack  g_spack;
__device__ double g_partial[MAX_BLOCKS];
__device__ unsigned int g_ticket;   // zero-init; last block resets (graph-replay safe)

// ---------------------------------------------------------------------------
__global__ void pack_kernel(
    const float* mW1, const float* mb1, const float* mW2, const float* mb2,
    const float* mW3, const float* mb3,
    const float* dW1, const float* db1, const float* dW2, const float* db2,
    const float* dW3, const float* db3,
    const float* oW1, const float* ob1, const float* oW2, const float* ob2,
    const float* oW3, const float* ob3)
{
    const float* W1[3] = {mW1, dW1, oW1};
    const float* B1[3] = {mb1, db1, ob1};
    const float* W2[3] = {mW2, dW2, oW2};
    const float* B2[3] = {mb2, db2, ob2};
    const float* W3[3] = {mW3, dW3, oW3};
    const float* B3[3] = {mb3, db3, ob3};
    const int OUT[3] = {4, 4, 6};
    int t = threadIdx.x;

    for (int i = t; i < 60; i += blockDim.x) {           // layer1 -> smem pack
        int m = i / 20, j = i % 20;
        g_spack.l1[m][j] = make_float4(W1[m][j], W1[m][20 + j], B1[m][j], 0.0f);
    }
    for (int i = t; i < 150; i += blockDim.x) {          // layer2 -> smem pack
        int m = i / 50, r = i % 50, k = r / 5, q = r % 5;
        g_spack.w2[m][k][q] = make_float4(
            W2[m][(4 * q + 0) * 10 + k], W2[m][(4 * q + 1) * 10 + k],
            W2[m][(4 * q + 2) * 10 + k], W2[m][(4 * q + 3) * 10 + k]);
    }
    for (int i = t; i < 54; i += blockDim.x) {           // layer3 -> constant
        int m = i / 18, r = i % 18, o = r / 3, q = r % 3;
        int Om = OUT[m];
        float v[4];
#pragma unroll
        for (int s = 0; s < 4; s++) {
            int k = 4 * q + s;
            v[s] = (k < 10 && o < Om) ? W3[m][k * Om + o] : 0.0f;
        }
        g_cstage.w3[m][o][q] = make_float4(v[0], v[1], v[2], v[3]);
    }
    for (int i = t; i < 30; i += blockDim.x) {
        int m = i / 10, k = i % 10;
        g_cstage.b2[m][k] = B2[m][k];
    }
    for (int i = t; i < 18; i += blockDim.x) {
        int m = i / 6, o = i % 6;
        g_cstage.b3[m][o] = (o < OUT[m]) ? B3[m][o] : 0.0f;
    }
}

// ---------------------------------------------------------------------------
template <int M, int OUT>
__device__ __forceinline__ void mlp_eval(const SPack* sp, float y0, float y1,
                                         float* out)
{
    float h[20];
#pragma unroll
    for (int j = 0; j < 20; j++) {
        float4 v = sp->l1[M][j];                        // LDS.128 broadcast
        h[j] = fmaxf(fmaf(v.x, y0, fmaf(v.y, y1, v.z)), 0.0f);
    }
    float h2[12];
#pragma unroll
    for (int k = 0; k < 10; k++) {
        float acc = c_w.b2[M][k];                       // scalar LDC
#pragma unroll
        for (int q = 0; q < 5; q++) {
            float4 v = sp->w2[M][k][q];                 // LDS.128 broadcast
            acc = fmaf(v.x, h[4 * q + 0], acc);
            acc = fmaf(v.y, h[4 * q + 1], acc);
            acc = fmaf(v.z, h[4 * q + 2], acc);
            acc = fmaf(v.w, h[4 * q + 3], acc);
        }
        h2[k] = fmaxf(acc, 0.0f);
    }
    h2[10] = 0.0f;
    h2[11] = 0.0f;
#pragma unroll
    for (int o = 0; o < OUT; o++) {
        float acc = c_w.b3[M][o];
#pragma unroll
        for (int q = 0; q < 3; q++) {
            float4 v = c_w.w3[M][o][q];                 // LDC.128
            acc = fmaf(v.x, h2[4 * q + 0], acc);
            acc = fmaf(v.y, h2[4 * q + 1], acc);
            acc = fmaf(v.z, h2[4 * q + 2], acc);
            acc = fmaf(v.w, h2[4 * q + 3], acc);
        }
        out[o] = acc;
    }
}

__device__ __forceinline__ float softplus_f(float x)
{
    // max(x,0) + log(1 + exp(-|x|)); fast-math MUFU path, abs err ~1e-6
    return fmaxf(x, 0.0f) + __logf(1.0f + __expf(-fabsf(x)));
}

// ---------------------------------------------------------------------------
__global__ void __launch_bounds__(NTHREADS)
vi_kernel(const float* __restrict__ y, const float* __restrict__ zs, int N,
          float* __restrict__ out)
{
    __shared__ SPack sp;
    __shared__ double sred[NTHREADS];
    __shared__ float wsum[NTHREADS / 32];
    __shared__ int sh_last;

    int tid = threadIdx.x;
    // Stage layer-1/2 weights global -> smem (210 float4, one per thread)
    {
        const float4* src = (const float4*)&g_spack;
        float4* dst = (float4*)&sp;
        if (tid < 210) dst[tid] = __ldg(&src[tid]);
    }
    __syncthreads();

    int n = blockIdx.x * NTHREADS + tid;
    float val = 0.0f;

    if (n < N) {
        // Front-load the only DRAM traffic (one 128B line/row).
        const float4* zp = (const float4*)zs + (size_t)n * 8;
        float4 zb[8];
#pragma unroll
        for (int p = 0; p < 8; p++) zb[p] = zp[p];

        float2 yv = ((const float2*)y)[n];

        float mu[4], ldr[4], off[6];
        mlp_eval<0, 4>(&sp, yv.x, yv.y, mu);
        mlp_eval<1, 4>(&sp, yv.x, yv.y, ldr);
        mlp_eval<2, 6>(&sp, yv.x, yv.y, off);

        float d0 = softplus_f(ldr[0]);
        float d1 = softplus_f(ldr[1]);
        float d2 = softplus_f(ldr[2]);
        float d3 = softplus_f(ldr[3]);

        float yx100 = yv.x * 100.0f;
        float yy100 = yv.y * 100.0f;

        float acc = 0.0f;
#pragma unroll
        for (int p = 0; p < 8; p++) {
            float4 z = zb[p];
            float xi0 = fmaf(d0, z.x, mu[0]);
            float xi1 = fmaf(d1, z.y, fmaf(off[0], z.x, mu[1]));
            float xi2 = fmaf(d2, z.z, fmaf(off[2], z.y, fmaf(off[1], z.x, mu[2])));
            float xi3 = fmaf(d3, z.w, fmaf(off[5], z.z,
                          fmaf(off[4], z.y, fmaf(off[3], z.x, mu[3]))));

            float a1 = xi1;
            float a2 = a1 + xi2;
            float a3 = a2 + xi3;
            float s1, c1, s2, c2, s3, c3;
            __sincosf(a1, &s1, &c1);
            __sincosf(a2, &s2, &c2);
            __sincosf(a3, &s3, &c3);

            float px = fmaf(0.5f, c1, fmaf(0.5f, c2, c3));
            float py = xi0 + fmaf(0.5f, s1, fmaf(0.5f, s2, s3));

            float rx = fmaf(-100.0f, px, yx100);
            float ry = fmaf(-100.0f, py, yy100);

            // acc -= 8*xi0^2 + 2*(xi1^2+xi2^2+xi3^2) + 0.5*(rx^2+ry^2)
            float s123 = fmaf(xi1, xi1, fmaf(xi2, xi2, xi3 * xi3));
            acc = fmaf(xi0 * -8.0f, xi0, acc);
            acc = fmaf(-2.0f, s123, acc);
            float r2 = fmaf(rx, rx, ry * ry);
            acc = fmaf(-0.5f, r2, acc);
        }

        float datafit = fmaf(acc, 0.125f, C_PER_SAMPLE);
        float entropy = C_ENTROPY + __logf(d0 * d1 * d2 * d3);
        val = datafit + entropy;
    }

    // ---- deterministic block reduction ----
#pragma unroll
    for (int o = 16; o > 0; o >>= 1)
        val += __shfl_down_sync(0xffffffffu, val, o);
    if ((tid & 31) == 0) wsum[tid >> 5] = val;
    __syncthreads();
    if (tid == 0) {
        double s = 0.0;
#pragma unroll
        for (int w = 0; w < NTHREADS / 32; w++) s += (double)wsum[w];
        g_partial[blockIdx.x] = s;
        __threadfence();
        unsigned t = atomicAdd(&g_ticket, 1u);
        sh_last = (t == gridDim.x - 1) ? 1 : 0;
    }
    __syncthreads();

    // ---- fused finalize: last block reduces partials deterministically ----
    if (sh_last) {
        __threadfence();
        double s = 0.0;
        for (int i = tid; i < (int)gridDim.x; i += NTHREADS)
            s += __ldcg(&g_partial[i]);
        sred[tid] = s;
        __syncthreads();
#pragma unroll
        for (int st = NTHREADS / 2; st > 0; st >>= 1) {
            if (tid < st) sred[tid] += sred[tid + st];
            __syncthreads();
        }
        if (tid == 0) {
            out[0] = (float)(sred[0] / (double)N);
            __threadfence();
            g_ticket = 0;   // reset for next graph replay
        }
    }
}

// ---------------------------------------------------------------------------
extern "C" void kernel_launch(void* const* d_in, const int* in_sizes, int n_in,
                              void* d_out, int out_size)
{
    const float* y  = (const float*)d_in[0];
    const float* zs = (const float*)d_in[1];
    int N = in_sizes[0] / 2;
    int nblocks = (N + NTHREADS - 1) / NTHREADS;
    if (nblocks > MAX_BLOCKS) nblocks = MAX_BLOCKS;

    pack_kernel<<<1, 128>>>(
        (const float*)d_in[2],  (const float*)d_in[3],  (const float*)d_in[4],
        (const float*)d_in[5],  (const float*)d_in[6],  (const float*)d_in[7],
        (const float*)d_in[8],  (const float*)d_in[9],  (const float*)d_in[10],
        (const float*)d_in[11], (const float*)d_in[12], (const float*)d_in[13],
        (const float*)d_in[14], (const float*)d_in[15], (const float*)d_in[16],
        (const float*)d_in[17], (const float*)d_in[18], (const float*)d_in[19]);

    void* caddr = nullptr;
    void* saddr = nullptr;
    cudaGetSymbolAddress(&caddr, c_w);
    cudaGetSymbolAddress(&saddr, g_cstage);
    cudaMemcpyAsync(caddr, saddr, sizeof(WConst), cudaMemcpyDeviceToDevice, 0);

    vi_kernel<<<nblocks, NTHREADS>>>(y, zs, N, (float*)d_out);
}

// round 6
// speedup vs baseline: 1.6510x; 1.1648x over previous
#include <cuda_runtime.h>

#define NTHREADS 256
#define MAX_BLOCKS 8192

#define C_PER_SAMPLE 7.1624450756f  // prior+lik constants per sample
#define C_ENTROPY    5.6757541328f  // 0.5*4*(1+log 2pi)

// Packed, padded weight layout in constant memory -> LDC with literal offsets.
struct WPack {
    float4 l1[3][20];    // (W1[0][j], W1[1][j], b1[j], 0)
    float4 w2[3][10][5]; // w2[m][k][q] = W2[4q..4q+3][k]
    float4 w3[3][6][3];  // w3[m][o][q] = W3[4q..4q+3][o] (k>=10 or o>=OUT -> 0)
    float4 b2v[3][3];    // b2 padded to 12, as 3 float4
    float4 b3v[3][2];    // b3 padded to 8,  as 2 float4
};

__constant__ WPack c_w;
__device__   WPack g_stage;
__device__ double g_partial[MAX_BLOCKS];
__device__ unsigned int g_ticket;   // zero-init; last block resets (graph-replay safe)

// ---------------------------------------------------------------------------
__global__ void pack_kernel(
    const float* mW1, const float* mb1, const float* mW2, const float* mb2,
    const float* mW3, const float* mb3,
    const float* dW1, const float* db1, const float* dW2, const float* db2,
    const float* dW3, const float* db3,
    const float* oW1, const float* ob1, const float* oW2, const float* ob2,
    const float* oW3, const float* ob3)
{
    const float* W1[3] = {mW1, dW1, oW1};
    const float* B1[3] = {mb1, db1, ob1};
    const float* W2[3] = {mW2, dW2, oW2};
    const float* B2[3] = {mb2, db2, ob2};
    const float* W3[3] = {mW3, dW3, oW3};
    const float* B3[3] = {mb3, db3, ob3};
    const int OUT[3] = {4, 4, 6};
    int t = threadIdx.x;

    for (int i = t; i < 60; i += blockDim.x) {
        int m = i / 20, j = i % 20;
        g_stage.l1[m][j] = make_float4(W1[m][j], W1[m][20 + j], B1[m][j], 0.0f);
    }
    for (int i = t; i < 150; i += blockDim.x) {
        int m = i / 50, r = i % 50, k = r / 5, q = r % 5;
        g_stage.w2[m][k][q] = make_float4(
            W2[m][(4 * q + 0) * 10 + k], W2[m][(4 * q + 1) * 10 + k],
            W2[m][(4 * q + 2) * 10 + k], W2[m][(4 * q + 3) * 10 + k]);
    }
    for (int i = t; i < 54; i += blockDim.x) {
        int m = i / 18, r = i % 18, o = r / 3, q = r % 3;
        int Om = OUT[m];
        float v[4];
#pragma unroll
        for (int s = 0; s < 4; s++) {
            int k = 4 * q + s;
            v[s] = (k < 10 && o < Om) ? W3[m][k * Om + o] : 0.0f;
        }
        g_stage.w3[m][o][q] = make_float4(v[0], v[1], v[2], v[3]);
    }
    for (int i = t; i < 36; i += blockDim.x) {      // b2 padded -> float4
        int m = i / 12, k = i % 12;
        ((float*)g_stage.b2v[m])[k] = (k < 10) ? B2[m][k] : 0.0f;
    }
    for (int i = t; i < 24; i += blockDim.x) {      // b3 padded -> float4
        int m = i / 8, o = i % 8;
        ((float*)g_stage.b3v[m])[o] = (o < OUT[m]) ? B3[m][o] : 0.0f;
    }
}

// ---------------------------------------------------------------------------
template <int M, int OUT>
__device__ __forceinline__ void mlp_eval(float y0, float y1, float* out)
{
    float h[20];
#pragma unroll
    for (int j = 0; j < 20; j++) {
        float4 v = c_w.l1[M][j];
        h[j] = fmaxf(fmaf(v.x, y0, fmaf(v.y, y1, v.z)), 0.0f);
    }
    // biases as vector LDC
    float b2[12];
#pragma unroll
    for (int t = 0; t < 3; t++) {
        float4 b = c_w.b2v[M][t];
        b2[4 * t] = b.x; b2[4 * t + 1] = b.y; b2[4 * t + 2] = b.z; b2[4 * t + 3] = b.w;
    }
    float h2[12];
#pragma unroll
    for (int k = 0; k < 10; k++) {
        float acc = b2[k];
#pragma unroll
        for (int q = 0; q < 5; q++) {
            float4 v = c_w.w2[M][k][q];
            acc = fmaf(v.x, h[4 * q + 0], acc);
            acc = fmaf(v.y, h[4 * q + 1], acc);
            acc = fmaf(v.z, h[4 * q + 2], acc);
            acc = fmaf(v.w, h[4 * q + 3], acc);
        }
        h2[k] = fmaxf(acc, 0.0f);
    }
    h2[10] = 0.0f;
    h2[11] = 0.0f;
    float b3[8];
#pragma unroll
    for (int t = 0; t < 2; t++) {
        float4 b = c_w.b3v[M][t];
        b3[4 * t] = b.x; b3[4 * t + 1] = b.y; b3[4 * t + 2] = b.z; b3[4 * t + 3] = b.w;
    }
#pragma unroll
    for (int o = 0; o < OUT; o++) {
        float acc = b3[o];
#pragma unroll
        for (int q = 0; q < 3; q++) {
            float4 v = c_w.w3[M][o][q];
            acc = fmaf(v.x, h2[4 * q + 0], acc);
            acc = fmaf(v.y, h2[4 * q + 1], acc);
            acc = fmaf(v.z, h2[4 * q + 2], acc);
            acc = fmaf(v.w, h2[4 * q + 3], acc);
        }
        out[o] = acc;
    }
}

__device__ __forceinline__ float softplus_f(float x)
{
    // max(x,0) + log(1 + exp(-|x|)); MUFU path, abs err ~1e-6
    return fmaxf(x, 0.0f) + __logf(1.0f + __expf(-fabsf(x)));
}

// ---------------------------------------------------------------------------
__global__ void __launch_bounds__(NTHREADS)
vi_kernel(const float* __restrict__ y, const float* __restrict__ zs, int N,
          float* __restrict__ out)
{
    __shared__ double sred[NTHREADS];
    __shared__ float wsum[NTHREADS / 32];
    __shared__ int sh_last;

    int tid = threadIdx.x;
    int n = blockIdx.x * NTHREADS + tid;
    float val = 0.0f;

    if (n < N) {
        // Front-load the only DRAM traffic (one 128B line/row).
        const float4* zp = (const float4*)zs + (size_t)n * 8;
        float4 zb[8];
#pragma unroll
        for (int p = 0; p < 8; p++) zb[p] = zp[p];

        float2 yv = ((const float2*)y)[n];

        float mu[4], ldr[4], off[6];
        mlp_eval<0, 4>(yv.x, yv.y, mu);
        mlp_eval<1, 4>(yv.x, yv.y, ldr);
        mlp_eval<2, 6>(yv.x, yv.y, off);

        float d0 = softplus_f(ldr[0]);
        float d1 = softplus_f(ldr[1]);
        float d2 = softplus_f(ldr[2]);
        float d3 = softplus_f(ldr[3]);

        float yx100 = yv.x * 100.0f;
        float yy100 = yv.y * 100.0f;

        float acc = 0.0f;
#pragma unroll
        for (int p = 0; p < 8; p++) {
            float4 z = zb[p];
            float xi0 = fmaf(d0, z.x, mu[0]);
            float xi1 = fmaf(d1, z.y, fmaf(off[0], z.x, mu[1]));
            float xi2 = fmaf(d2, z.z, fmaf(off[2], z.y, fmaf(off[1], z.x, mu[2])));
            float xi3 = fmaf(d3, z.w, fmaf(off[5], z.z,
                          fmaf(off[4], z.y, fmaf(off[3], z.x, mu[3]))));

            float a1 = xi1;
            float a2 = a1 + xi2;
            float a3 = a2 + xi3;
            float s1, c1, s2, c2, s3, c3;
            __sincosf(a1, &s1, &c1);
            __sincosf(a2, &s2, &c2);
            __sincosf(a3, &s3, &c3);

            float px = fmaf(0.5f, c1, fmaf(0.5f, c2, c3));
            float py = xi0 + fmaf(0.5f, s1, fmaf(0.5f, s2, s3));

            float rx = fmaf(-100.0f, px, yx100);
            float ry = fmaf(-100.0f, py, yy100);

            // acc -= 8*xi0^2 + 2*(xi1^2+xi2^2+xi3^2) + 0.5*(rx^2+ry^2)
            float s123 = fmaf(xi1, xi1, fmaf(xi2, xi2, xi3 * xi3));
            acc = fmaf(xi0 * -8.0f, xi0, acc);
            acc = fmaf(-2.0f, s123, acc);
            float r2 = fmaf(rx, rx, ry * ry);
            acc = fmaf(-0.5f, r2, acc);
        }

        float datafit = fmaf(acc, 0.125f, C_PER_SAMPLE);
        float entropy = C_ENTROPY + __logf(d0 * d1 * d2 * d3);
        val = datafit + entropy;
    }

    // ---- deterministic block reduction ----
#pragma unroll
    for (int o = 16; o > 0; o >>= 1)
        val += __shfl_down_sync(0xffffffffu, val, o);
    if ((tid & 31) == 0) wsum[tid >> 5] = val;
    __syncthreads();
    if (tid == 0) {
        double s = 0.0;
#pragma unroll
        for (int w = 0; w < NTHREADS / 32; w++) s += (double)wsum[w];
        g_partial[blockIdx.x] = s;
        __threadfence();
        unsigned t = atomicAdd(&g_ticket, 1u);
        sh_last = (t == gridDim.x - 1) ? 1 : 0;
    }
    __syncthreads();

    // ---- fused finalize: last block reduces partials deterministically ----
    if (sh_last) {
        __threadfence();
        double s = 0.0;
        for (int i = tid; i < (int)gridDim.x; i += NTHREADS)
            s += __ldcg(&g_partial[i]);
        sred[tid] = s;
        __syncthreads();
#pragma unroll
        for (int st = NTHREADS / 2; st > 0; st >>= 1) {
            if (tid < st) sred[tid] += sred[tid + st];
            __syncthreads();
        }
        if (tid == 0) {
            out[0] = (float)(sred[0] / (double)N);
            __threadfence();
            g_ticket = 0;   // reset for next graph replay
        }
    }
}

// ---------------------------------------------------------------------------
extern "C" void kernel_launch(void* const* d_in, const int* in_sizes, int n_in,
                              void* d_out, int out_size)
{
    const float* y  = (const float*)d_in[0];
    const float* zs = (const float*)d_in[1];
    int N = in_sizes[0] / 2;
    int nblocks = (N + NTHREADS - 1) / NTHREADS;
    if (nblocks > MAX_BLOCKS) nblocks = MAX_BLOCKS;

    pack_kernel<<<1, 128>>>(
        (const float*)d_in[2],  (const float*)d_in[3],  (const float*)d_in[4],
        (const float*)d_in[5],  (const float*)d_in[6],  (const float*)d_in[7],
        (const float*)d_in[8],  (const float*)d_in[9],  (const float*)d_in[10],
        (const float*)d_in[11], (const float*)d_in[12], (const float*)d_in[13],
        (const float*)d_in[14], (const float*)d_in[15], (const float*)d_in[16],
        (const float*)d_in[17], (const float*)d_in[18], (const float*)d_in[19]);

    void* caddr = nullptr;
    void* saddr = nullptr;
    cudaGetSymbolAddress(&caddr, c_w);
    cudaGetSymbolAddress(&saddr, g_stage);
    cudaMemcpyAsync(caddr, saddr, sizeof(WPack), cudaMemcpyDeviceToDevice, 0);

    vi_kernel<<<nblocks, NTHREADS>>>(y, zs, N, (float*)d_out);
}

// round 7
// speedup vs baseline: 1.7240x; 1.0442x over previous
#include <cuda_runtime.h>

#define NTHREADS 256
#define MAX_BLOCKS 8192

#define C_PER_SAMPLE 7.1624450756f  // prior+lik constants per sample
#define C_ENTROPY    5.6757541328f  // 0.5*4*(1+log 2pi)

// Packed, padded weight layout in constant memory -> LDC with literal offsets.
struct WPack {
    float4 l1[3][20];    // (W1[0][j], W1[1][j], b1[j], 0)
    float4 w2[3][10][5]; // w2[m][k][q] = W2[4q..4q+3][k]
    float4 w3[3][6][3];  // w3[m][o][q] = W3[4q..4q+3][o] (k>=10 or o>=OUT -> 0)
    float4 b2v[3][3];    // b2 padded to 12, as 3 float4
    float4 b3v[3][2];    // b3 padded to 8,  as 2 float4
};

__constant__ WPack c_w;
__device__   WPack g_stage;
__device__ double g_partial[MAX_BLOCKS];
__device__ unsigned int g_ticket;   // zero-init; last block resets (graph-replay safe)

// ---------------------------------------------------------------------------
__global__ void pack_kernel(
    const float* mW1, const float* mb1, const float* mW2, const float* mb2,
    const float* mW3, const float* mb3,
    const float* dW1, const float* db1, const float* dW2, const float* db2,
    const float* dW3, const float* db3,
    const float* oW1, const float* ob1, const float* oW2, const float* ob2,
    const float* oW3, const float* ob3)
{
    const float* W1[3] = {mW1, dW1, oW1};
    const float* B1[3] = {mb1, db1, ob1};
    const float* W2[3] = {mW2, dW2, oW2};
    const float* B2[3] = {mb2, db2, ob2};
    const float* W3[3] = {mW3, dW3, oW3};
    const float* B3[3] = {mb3, db3, ob3};
    const int OUT[3] = {4, 4, 6};
    int t = threadIdx.x;

    for (int i = t; i < 60; i += blockDim.x) {
        int m = i / 20, j = i % 20;
        g_stage.l1[m][j] = make_float4(W1[m][j], W1[m][20 + j], B1[m][j], 0.0f);
    }
    for (int i = t; i < 150; i += blockDim.x) {
        int m = i / 50, r = i % 50, k = r / 5, q = r % 5;
        g_stage.w2[m][k][q] = make_float4(
            W2[m][(4 * q + 0) * 10 + k], W2[m][(4 * q + 1) * 10 + k],
            W2[m][(4 * q + 2) * 10 + k], W2[m][(4 * q + 3) * 10 + k]);
    }
    for (int i = t; i < 54; i += blockDim.x) {
        int m = i / 18, r = i % 18, o = r / 3, q = r % 3;
        int Om = OUT[m];
        float v[4];
#pragma unroll
        for (int s = 0; s < 4; s++) {
            int k = 4 * q + s;
            v[s] = (k < 10 && o < Om) ? W3[m][k * Om + o] : 0.0f;
        }
        g_stage.w3[m][o][q] = make_float4(v[0], v[1], v[2], v[3]);
    }
    for (int i = t; i < 36; i += blockDim.x) {
        int m = i / 12, k = i % 12;
        ((float*)g_stage.b2v[m])[k] = (k < 10) ? B2[m][k] : 0.0f;
    }
    for (int i = t; i < 24; i += blockDim.x) {
        int m = i / 8, o = i % 8;
        ((float*)g_stage.b3v[m])[o] = (o < OUT[m]) ? B3[m][o] : 0.0f;
    }
}

// ---------------------------------------------------------------------------
template <int M, int OUT>
__device__ __forceinline__ void mlp_eval(float y0, float y1, float* out)
{
    float h[20];
#pragma unroll
    for (int j = 0; j < 20; j++) {
        float4 v = c_w.l1[M][j];
        h[j] = fmaxf(fmaf(v.x, y0, fmaf(v.y, y1, v.z)), 0.0f);
    }
    float h2[12];
#pragma unroll
    for (int k = 0; k < 10; k++) {
        // bias component straight from constant (no unpack array)
        float4 bq = c_w.b2v[M][k >> 2];
        float acc = (k & 3) == 0 ? bq.x : (k & 3) == 1 ? bq.y
                  : (k & 3) == 2 ? bq.z : bq.w;
#pragma unroll
        for (int q = 0; q < 5; q++) {
            float4 v = c_w.w2[M][k][q];
            acc = fmaf(v.x, h[4 * q + 0], acc);
            acc = fmaf(v.y, h[4 * q + 1], acc);
            acc = fmaf(v.z, h[4 * q + 2], acc);
            acc = fmaf(v.w, h[4 * q + 3], acc);
        }
        h2[k] = fmaxf(acc, 0.0f);
    }
    h2[10] = 0.0f;
    h2[11] = 0.0f;
#pragma unroll
    for (int o = 0; o < OUT; o++) {
        float4 bq = c_w.b3v[M][o >> 2];
        float acc = (o & 3) == 0 ? bq.x : (o & 3) == 1 ? bq.y
                  : (o & 3) == 2 ? bq.z : bq.w;
#pragma unroll
        for (int q = 0; q < 3; q++) {
            float4 v = c_w.w3[M][o][q];
            acc = fmaf(v.x, h2[4 * q + 0], acc);
            acc = fmaf(v.y, h2[4 * q + 1], acc);
            acc = fmaf(v.z, h2[4 * q + 2], acc);
            acc = fmaf(v.w, h2[4 * q + 3], acc);
        }
        out[o] = acc;
    }
}

__device__ __forceinline__ float softplus_f(float x)
{
    // max(x,0) + log(1 + exp(-|x|)); MUFU path, abs err ~1e-6
    return fmaxf(x, 0.0f) + __logf(1.0f + __expf(-fabsf(x)));
}

// ---------------------------------------------------------------------------
// launch_bounds(256, 5): reg budget 51 -> no spills for ~45-reg live set.
__global__ void __launch_bounds__(NTHREADS, 5)
vi_kernel(const float* __restrict__ y, const float* __restrict__ zs, int N,
          float* __restrict__ out)
{
    __shared__ double sred[NTHREADS];
    __shared__ float wsum[NTHREADS / 32];
    __shared__ int sh_last;

    int tid = threadIdx.x;
    int n = blockIdx.x * NTHREADS + tid;
    float val = 0.0f;

    if (n < N) {
        const float4* zp = (const float4*)zs + (size_t)n * 8;
        // Prefetch first z and y; latency hides under the MLP block.
        float4 znext = zp[0];
        float2 yv = ((const float2*)y)[n];

        float mu[4], ldr[4], off[6];
        mlp_eval<0, 4>(yv.x, yv.y, mu);
        mlp_eval<1, 4>(yv.x, yv.y, ldr);
        mlp_eval<2, 6>(yv.x, yv.y, off);

        float d0 = softplus_f(ldr[0]);
        float d1 = softplus_f(ldr[1]);
        float d2 = softplus_f(ldr[2]);
        float d3 = softplus_f(ldr[3]);

        float yx100 = yv.x * 100.0f;
        float yy100 = yv.y * 100.0f;

        float acc = 0.0f;
#pragma unroll
        for (int p = 0; p < 8; p++) {
            float4 z = znext;
            if (p < 7) znext = zp[p + 1];   // software pipeline: 1 load in flight

            float xi0 = fmaf(d0, z.x, mu[0]);
            float xi1 = fmaf(d1, z.y, fmaf(off[0], z.x, mu[1]));
            float xi2 = fmaf(d2, z.z, fmaf(off[2], z.y, fmaf(off[1], z.x, mu[2])));
            float xi3 = fmaf(d3, z.w, fmaf(off[5], z.z,
                          fmaf(off[4], z.y, fmaf(off[3], z.x, mu[3]))));

            float a1 = xi1;
            float a2 = a1 + xi2;
            float a3 = a2 + xi3;
            float s1, c1, s2, c2, s3, c3;
            __sincosf(a1, &s1, &c1);
            __sincosf(a2, &s2, &c2);
            __sincosf(a3, &s3, &c3);

            float px = fmaf(0.5f, c1, fmaf(0.5f, c2, c3));
            float py = xi0 + fmaf(0.5f, s1, fmaf(0.5f, s2, s3));

            float rx = fmaf(-100.0f, px, yx100);
            float ry = fmaf(-100.0f, py, yy100);

            // acc -= 8*xi0^2 + 2*(xi1^2+xi2^2+xi3^2) + 0.5*(rx^2+ry^2)
            float s123 = fmaf(xi1, xi1, fmaf(xi2, xi2, xi3 * xi3));
            acc = fmaf(xi0 * -8.0f, xi0, acc);
            acc = fmaf(-2.0f, s123, acc);
            float r2 = fmaf(rx, rx, ry * ry);
            acc = fmaf(-0.5f, r2, acc);
        }

        float datafit = fmaf(acc, 0.125f, C_PER_SAMPLE);
        float entropy = C_ENTROPY + __logf(d0 * d1 * d2 * d3);
        val = datafit + entropy;
    }

    // ---- deterministic block reduction ----
#pragma unroll
    for (int o = 16; o > 0; o >>= 1)
        val += __shfl_down_sync(0xffffffffu, val, o);
    if ((tid & 31) == 0) wsum[tid >> 5] = val;
    __syncthreads();
    if (tid == 0) {
        double s = 0.0;
#pragma unroll
        for (int w = 0; w < NTHREADS / 32; w++) s += (double)wsum[w];
        g_partial[blockIdx.x] = s;
        __threadfence();
        unsigned t = atomicAdd(&g_ticket, 1u);
        sh_last = (t == gridDim.x - 1) ? 1 : 0;
    }
    __syncthreads();

    // ---- fused finalize: last block reduces partials deterministically ----
    if (sh_last) {
        __threadfence();
        double s = 0.0;
        for (int i = tid; i < (int)gridDim.x; i += NTHREADS)
            s += __ldcg(&g_partial[i]);
        sred[tid] = s;
        __syncthreads();
#pragma unroll
        for (int st = NTHREADS / 2; st > 0; st >>= 1) {
            if (tid < st) sred[tid] += sred[tid + st];
            __syncthreads();
        }
        if (tid == 0) {
            out[0] = (float)(sred[0] / (double)N);
            __threadfence();
            g_ticket = 0;   // reset for next graph replay
        }
    }
}

// ---------------------------------------------------------------------------
extern "C" void kernel_launch(void* const* d_in, const int* in_sizes, int n_in,
                              void* d_out, int out_size)
{
    const float* y  = (const float*)d_in[0];
    const float* zs = (const float*)d_in[1];
    int N = in_sizes[0] / 2;
    int nblocks = (N + NTHREADS - 1) / NTHREADS;
    if (nblocks > MAX_BLOCKS) nblocks = MAX_BLOCKS;

    pack_kernel<<<1, 128>>>(
        (const float*)d_in[2],  (const float*)d_in[3],  (const float*)d_in[4],
        (const float*)d_in[5],  (const float*)d_in[6],  (const float*)d_in[7],
        (const float*)d_in[8],  (const float*)d_in[9],  (const float*)d_in[10],
        (const float*)d_in[11], (const float*)d_in[12], (const float*)d_in[13],
        (const float*)d_in[14], (const float*)d_in[15], (const float*)d_in[16],
        (const float*)d_in[17], (const float*)d_in[18], (const float*)d_in[19]);

    void* caddr = nullptr;
    void* saddr = nullptr;
    cudaGetSymbolAddress(&caddr, c_w);
    cudaGetSymbolAddress(&saddr, g_stage);
    cudaMemcpyAsync(caddr, saddr, sizeof(WPack), cudaMemcpyDeviceToDevice, 0);

    vi_kernel<<<nblocks, NTHREADS>>>(y, zs, N, (float*)d_out);
}

// round 8
// speedup vs baseline: 1.7894x; 1.0379x over previous
#include <cuda_runtime.h>

#define NTHREADS 256
#define MAX_BLOCKS 8192

#define C_PER_SAMPLE 7.1624450756f  // prior+lik constants per sample
#define C_ENTROPY    5.6757541328f  // 0.5*4*(1+log 2pi)

// Packed, padded weight layout in constant memory -> LDC with literal offsets.
struct WPack {
    float4 l1[3][20];    // (W1[0][j], W1[1][j], b1[j], 0)
    float4 w2[3][10][5]; // w2[m][k][q] = W2[4q..4q+3][k]
    float4 w3[3][6][3];  // w3[m][o][q] = W3[4q..4q+3][o] (k>=10 or o>=OUT -> 0)
    float4 b2v[3][3];    // b2 padded to 12
    float4 b3v[3][2];    // b3 padded to 8
};

__constant__ WPack c_w;
__device__   WPack g_stage;
__device__ double g_partial[MAX_BLOCKS];
__device__ unsigned int g_ticket;   // zero-init; last block resets (graph-replay safe)

// ---------------------------------------------------------------------------
__global__ void pack_kernel(
    const float* mW1, const float* mb1, const float* mW2, const float* mb2,
    const float* mW3, const float* mb3,
    const float* dW1, const float* db1, const float* dW2, const float* db2,
    const float* dW3, const float* db3,
    const float* oW1, const float* ob1, const float* oW2, const float* ob2,
    const float* oW3, const float* ob3)
{
    const float* W1[3] = {mW1, dW1, oW1};
    const float* B1[3] = {mb1, db1, ob1};
    const float* W2[3] = {mW2, dW2, oW2};
    const float* B2[3] = {mb2, db2, ob2};
    const float* W3[3] = {mW3, dW3, oW3};
    const float* B3[3] = {mb3, db3, ob3};
    const int OUT[3] = {4, 4, 6};
    int t = threadIdx.x;

    for (int i = t; i < 60; i += blockDim.x) {
        int m = i / 20, j = i % 20;
        g_stage.l1[m][j] = make_float4(W1[m][j], W1[m][20 + j], B1[m][j], 0.0f);
    }
    for (int i = t; i < 150; i += blockDim.x) {
        int m = i / 50, r = i % 50, k = r / 5, q = r % 5;
        g_stage.w2[m][k][q] = make_float4(
            W2[m][(4 * q + 0) * 10 + k], W2[m][(4 * q + 1) * 10 + k],
            W2[m][(4 * q + 2) * 10 + k], W2[m][(4 * q + 3) * 10 + k]);
    }
    for (int i = t; i < 54; i += blockDim.x) {
        int m = i / 18, r = i % 18, o = r / 3, q = r % 3;
        int Om = OUT[m];
        float v[4];
#pragma unroll
        for (int s = 0; s < 4; s++) {
            int k = 4 * q + s;
            v[s] = (k < 10 && o < Om) ? W3[m][k * Om + o] : 0.0f;
        }
        g_stage.w3[m][o][q] = make_float4(v[0], v[1], v[2], v[3]);
    }
    for (int i = t; i < 36; i += blockDim.x) {
        int m = i / 12, k = i % 12;
        ((float*)g_stage.b2v[m])[k] = (k < 10) ? B2[m][k] : 0.0f;
    }
    for (int i = t; i < 24; i += blockDim.x) {
        int m = i / 8, o = i % 8;
        ((float*)g_stage.b3v[m])[o] = (o < OUT[m]) ? B3[m][o] : 0.0f;
    }
}

// ---------------------------------------------------------------------------
// Two data rows per thread: every LDC.128 weight load feeds BOTH rows.
template <int M, int OUT>
__device__ __forceinline__ void mlp_eval2r(float y0A, float y1A,
                                           float y0B, float y1B,
                                           float* outA, float* outB)
{
    float hA[20], hB[20];
#pragma unroll
    for (int j = 0; j < 20; j++) {
        float4 v = c_w.l1[M][j];
        hA[j] = fmaxf(fmaf(v.x, y0A, fmaf(v.y, y1A, v.z)), 0.0f);
        hB[j] = fmaxf(fmaf(v.x, y0B, fmaf(v.y, y1B, v.z)), 0.0f);
    }
    float h2A[12], h2B[12];
#pragma unroll
    for (int k = 0; k < 10; k++) {
        float4 bq = c_w.b2v[M][k >> 2];
        float b = (k & 3) == 0 ? bq.x : (k & 3) == 1 ? bq.y
                : (k & 3) == 2 ? bq.z : bq.w;
        float aA = b, aB = b;
#pragma unroll
        for (int q = 0; q < 5; q++) {
            float4 v = c_w.w2[M][k][q];
            aA = fmaf(v.x, hA[4 * q + 0], aA);
            aB = fmaf(v.x, hB[4 * q + 0], aB);
            aA = fmaf(v.y, hA[4 * q + 1], aA);
            aB = fmaf(v.y, hB[4 * q + 1], aB);
            aA = fmaf(v.z, hA[4 * q + 2], aA);
            aB = fmaf(v.z, hB[4 * q + 2], aB);
            aA = fmaf(v.w, hA[4 * q + 3], aA);
            aB = fmaf(v.w, hB[4 * q + 3], aB);
        }
        h2A[k] = fmaxf(aA, 0.0f);
        h2B[k] = fmaxf(aB, 0.0f);
    }
    h2A[10] = 0.0f; h2A[11] = 0.0f;
    h2B[10] = 0.0f; h2B[11] = 0.0f;
#pragma unroll
    for (int o = 0; o < OUT; o++) {
        float4 bq = c_w.b3v[M][o >> 2];
        float b = (o & 3) == 0 ? bq.x : (o & 3) == 1 ? bq.y
                : (o & 3) == 2 ? bq.z : bq.w;
        float aA = b, aB = b;
#pragma unroll
        for (int q = 0; q < 3; q++) {
            float4 v = c_w.w3[M][o][q];
            aA = fmaf(v.x, h2A[4 * q + 0], aA);
            aB = fmaf(v.x, h2B[4 * q + 0], aB);
            aA = fmaf(v.y, h2A[4 * q + 1], aA);
            aB = fmaf(v.y, h2B[4 * q + 1], aB);
            aA = fmaf(v.z, h2A[4 * q + 2], aA);
            aB = fmaf(v.z, h2B[4 * q + 2], aB);
            aA = fmaf(v.w, h2A[4 * q + 3], aA);
            aB = fmaf(v.w, h2B[4 * q + 3], aB);
        }
        outA[o] = aA;
        outB[o] = aB;
    }
}

__device__ __forceinline__ float softplus_f(float x)
{
    return fmaxf(x, 0.0f) + __logf(1.0f + __expf(-fabsf(x)));
}

// Per-row sample-loop body; returns acc contribution for one sample.
__device__ __forceinline__ float sample_term(
    const float4 z, const float* mu, const float* off,
    float d0, float d1, float d2, float d3, float yx100, float yy100)
{
    float xi0 = fmaf(d0, z.x, mu[0]);
    float xi1 = fmaf(d1, z.y, fmaf(off[0], z.x, mu[1]));
    float xi2 = fmaf(d2, z.z, fmaf(off[2], z.y, fmaf(off[1], z.x, mu[2])));
    float xi3 = fmaf(d3, z.w, fmaf(off[5], z.z,
                  fmaf(off[4], z.y, fmaf(off[3], z.x, mu[3]))));

    float a2 = xi1 + xi2;
    float a3 = a2 + xi3;
    float s1, c1, s2, c2, s3, c3;
    __sincosf(xi1, &s1, &c1);
    __sincosf(a2,  &s2, &c2);
    __sincosf(a3,  &s3, &c3);

    float px = fmaf(0.5f, c1, fmaf(0.5f, c2, c3));
    float py = xi0 + fmaf(0.5f, s1, fmaf(0.5f, s2, s3));

    float rx = fmaf(-100.0f, px, yx100);
    float ry = fmaf(-100.0f, py, yy100);

    float s123 = fmaf(xi1, xi1, fmaf(xi2, xi2, xi3 * xi3));
    float t = fmaf(xi0 * -8.0f, xi0, fmaf(-2.0f, s123, 0.0f));
    float r2 = fmaf(rx, rx, ry * ry);
    return fmaf(-0.5f, r2, t);
}

// ---------------------------------------------------------------------------
__global__ void __launch_bounds__(NTHREADS, 3)
vi_kernel(const float* __restrict__ y, const float* __restrict__ zs, int N,
          float* __restrict__ out)
{
    __shared__ double sred[NTHREADS];
    __shared__ float wsum[NTHREADS / 32];
    __shared__ int sh_last;

    int tid = threadIdx.x;
    int g = blockIdx.x * NTHREADS + tid;
    int n0 = 2 * g, n1 = n0 + 1;
    float val = 0.0f;

    if (n0 < N) {
        bool two = (n1 < N);
        float4 yv;
        if (two) {
            yv = ((const float4*)y)[g];
        } else {
            float2 ya = ((const float2*)y)[n0];
            yv = make_float4(ya.x, ya.y, ya.x, ya.y);
            n1 = n0;
        }

        const float4* zpA = (const float4*)zs + (size_t)n0 * 8;
        const float4* zpB = (const float4*)zs + (size_t)n1 * 8;
        float4 zA = zpA[0];          // prefetch; hides under MLP block
        float4 zB = zpB[0];

        float muA[4], muB[4], ldA[4], ldB[4], ofA[6], ofB[6];
        mlp_eval2r<0, 4>(yv.x, yv.y, yv.z, yv.w, muA, muB);
        mlp_eval2r<1, 4>(yv.x, yv.y, yv.z, yv.w, ldA, ldB);
        mlp_eval2r<2, 6>(yv.x, yv.y, yv.z, yv.w, ofA, ofB);

        float d0A = softplus_f(ldA[0]), d0B = softplus_f(ldB[0]);
        float d1A = softplus_f(ldA[1]), d1B = softplus_f(ldB[1]);
        float d2A = softplus_f(ldA[2]), d2B = softplus_f(ldB[2]);
        float d3A = softplus_f(ldA[3]), d3B = softplus_f(ldB[3]);

        float yxA = yv.x * 100.0f, yyA = yv.y * 100.0f;
        float yxB = yv.z * 100.0f, yyB = yv.w * 100.0f;

        float accA = 0.0f, accB = 0.0f;
#pragma unroll
        for (int p = 0; p < 8; p++) {
            float4 za = zA, zb = zB;
            if (p < 7) { zA = zpA[p + 1]; zB = zpB[p + 1]; }
            accA += sample_term(za, muA, ofA, d0A, d1A, d2A, d3A, yxA, yyA);
            accB += sample_term(zb, muB, ofB, d0B, d1B, d2B, d3B, yxB, yyB);
        }

        float vA = fmaf(accA, 0.125f, C_PER_SAMPLE) + C_ENTROPY +
                   __logf(d0A * d1A * d2A * d3A);
        float vB = fmaf(accB, 0.125f, C_PER_SAMPLE) + C_ENTROPY +
                   __logf(d0B * d1B * d2B * d3B);
        val = two ? (vA + vB) : vA;
    }

    // ---- deterministic block reduction ----
#pragma unroll
    for (int o = 16; o > 0; o >>= 1)
        val += __shfl_down_sync(0xffffffffu, val, o);
    if ((tid & 31) == 0) wsum[tid >> 5] = val;
    __syncthreads();
    if (tid == 0) {
        double s = 0.0;
#pragma unroll
        for (int w = 0; w < NTHREADS / 32; w++) s += (double)wsum[w];
        g_partial[blockIdx.x] = s;
        __threadfence();
        unsigned t = atomicAdd(&g_ticket, 1u);
        sh_last = (t == gridDim.x - 1) ? 1 : 0;
    }
    __syncthreads();

    // ---- fused finalize: last block reduces partials deterministically ----
    if (sh_last) {
        __threadfence();
        double s = 0.0;
        for (int i = tid; i < (int)gridDim.x; i += NTHREADS)
            s += __ldcg(&g_partial[i]);
        sred[tid] = s;
        __syncthreads();
#pragma unroll
        for (int st = NTHREADS / 2; st > 0; st >>= 1) {
            if (tid < st) sred[tid] += sred[tid + st];
            __syncthreads();
        }
        if (tid == 0) {
            out[0] = (float)(sred[0] / (double)N);
            __threadfence();
            g_ticket = 0;   // reset for next graph replay
        }
    }
}

// ---------------------------------------------------------------------------
extern "C" void kernel_launch(void* const* d_in, const int* in_sizes, int n_in,
                              void* d_out, int out_size)
{
    const float* y  = (const float*)d_in[0];
    const float* zs = (const float*)d_in[1];
    int N = in_sizes[0] / 2;
    int npairs = (N + 1) / 2;
    int nblocks = (npairs + NTHREADS - 1) / NTHREADS;
    if (nblocks > MAX_BLOCKS) nblocks = MAX_BLOCKS;

    pack_kernel<<<1, 128>>>(
        (const float*)d_in[2],  (const float*)d_in[3],  (const float*)d_in[4],
        (const float*)d_in[5],  (const float*)d_in[6],  (const float*)d_in[7],
        (const float*)d_in[8],  (const float*)d_in[9],  (const float*)d_in[10],
        (const float*)d_in[11], (const float*)d_in[12], (const float*)d_in[13],
        (const float*)d_in[14], (const float*)d_in[15], (const float*)d_in[16],
        (const float*)d_in[17], (const float*)d_in[18], (const float*)d_in[19]);

    void* caddr = nullptr;
    void* saddr = nullptr;
    cudaGetSymbolAddress(&caddr, c_w);
    cudaGetSymbolAddress(&saddr, g_stage);
    cudaMemcpyAsync(caddr, saddr, sizeof(WPack), cudaMemcpyDeviceToDevice, 0);

    vi_kernel<<<nblocks, NTHREADS>>>(y, zs, N, (float*)d_out);
}

// round 9
// speedup vs baseline: 1.9270x; 1.0769x over previous
#include <cuda_runtime.h>

#define NTHREADS 256
#define MAX_BLOCKS 8192

#define C_PER_SAMPLE 7.1624450756f  // prior+lik constants per sample
#define C_ENTROPY    5.6757541328f  // 0.5*4*(1+log 2pi)

// Constant-memory weights, packed for the j-streaming schedule.
struct WPack {
    float4 l1 [3][20];     // (W1[0][j], W1[1][j], b1[j], 0)
    float4 w2j[3][20][3];  // w2j[m][j][t] = W2[j][4t..4t+3] (k>=10 -> 0)
    float4 w3 [3][6][3];   // w3[m][o][q] = W3[4q..4q+3][o] (pad -> 0)
    float4 b2v[3][3];      // b2 padded to 12
    float4 b3v[3][2];      // b3 padded to 8
};

__constant__ WPack c_w;
__device__   WPack g_stage;
__device__ double g_partial[MAX_BLOCKS];
__device__ unsigned int g_ticket;   // zero-init; last block resets (graph-replay safe)

// ---------------------------------------------------------------------------
__global__ void pack_kernel(
    const float* mW1, const float* mb1, const float* mW2, const float* mb2,
    const float* mW3, const float* mb3,
    const float* dW1, const float* db1, const float* dW2, const float* db2,
    const float* dW3, const float* db3,
    const float* oW1, const float* ob1, const float* oW2, const float* ob2,
    const float* oW3, const float* ob3)
{
    const float* W1[3] = {mW1, dW1, oW1};
    const float* B1[3] = {mb1, db1, ob1};
    const float* W2[3] = {mW2, dW2, oW2};
    const float* B2[3] = {mb2, db2, ob2};
    const float* W3[3] = {mW3, dW3, oW3};
    const float* B3[3] = {mb3, db3, ob3};
    const int OUT[3] = {4, 4, 6};
    int t = threadIdx.x;

    for (int i = t; i < 60; i += blockDim.x) {
        int m = i / 20, j = i % 20;
        g_stage.l1[m][j] = make_float4(W1[m][j], W1[m][20 + j], B1[m][j], 0.0f);
    }
    for (int i = t; i < 180; i += blockDim.x) {        // w2 by input column j
        int m = i / 60, r = i % 60, j = r / 3, tt = r % 3;
        float v[4];
#pragma unroll
        for (int s = 0; s < 4; s++) {
            int k = 4 * tt + s;
            v[s] = (k < 10) ? W2[m][j * 10 + k] : 0.0f;
        }
        g_stage.w2j[m][j][tt] = make_float4(v[0], v[1], v[2], v[3]);
    }
    for (int i = t; i < 54; i += blockDim.x) {
        int m = i / 18, r = i % 18, o = r / 3, q = r % 3;
        int Om = OUT[m];
        float v[4];
#pragma unroll
        for (int s = 0; s < 4; s++) {
            int k = 4 * q + s;
            v[s] = (k < 10 && o < Om) ? W3[m][k * Om + o] : 0.0f;
        }
        g_stage.w3[m][o][q] = make_float4(v[0], v[1], v[2], v[3]);
    }
    for (int i = t; i < 36; i += blockDim.x) {
        int m = i / 12, k = i % 12;
        ((float*)g_stage.b2v[m])[k] = (k < 10) ? B2[m][k] : 0.0f;
    }
    for (int i = t; i < 24; i += blockDim.x) {
        int m = i / 8, o = i % 8;
        ((float*)g_stage.b3v[m])[o] = (o < OUT[m]) ? B3[m][o] : 0.0f;
    }
}

// ---------------------------------------------------------------------------
// Two data rows per thread, layers 1+2 fused (j-streaming: no h[20] storage).
template <int M, int OUT>
__device__ __forceinline__ void mlp_eval2r(float y0A, float y1A,
                                           float y0B, float y1B,
                                           float* outA, float* outB)
{
    float aA[12], aB[12];
#pragma unroll
    for (int tt = 0; tt < 3; tt++) {
        float4 b = c_w.b2v[M][tt];
        aA[4 * tt + 0] = b.x; aB[4 * tt + 0] = b.x;
        aA[4 * tt + 1] = b.y; aB[4 * tt + 1] = b.y;
        aA[4 * tt + 2] = b.z; aB[4 * tt + 2] = b.z;
        aA[4 * tt + 3] = b.w; aB[4 * tt + 3] = b.w;
    }
#pragma unroll
    for (int j = 0; j < 20; j++) {
        float4 v = c_w.l1[M][j];
        float hA = fmaxf(fmaf(v.x, y0A, fmaf(v.y, y1A, v.z)), 0.0f);
        float hB = fmaxf(fmaf(v.x, y0B, fmaf(v.y, y1B, v.z)), 0.0f);
#pragma unroll
        for (int tt = 0; tt < 3; tt++) {
            float4 w = c_w.w2j[M][j][tt];
            aA[4 * tt + 0] = fmaf(w.x, hA, aA[4 * tt + 0]);
            aB[4 * tt + 0] = fmaf(w.x, hB, aB[4 * tt + 0]);
            aA[4 * tt + 1] = fmaf(w.y, hA, aA[4 * tt + 1]);
            aB[4 * tt + 1] = fmaf(w.y, hB, aB[4 * tt + 1]);
            if (tt < 2) {   // k = 8..9 only in tt==2; z,w lanes there are pads
                aA[4 * tt + 2] = fmaf(w.z, hA, aA[4 * tt + 2]);
                aB[4 * tt + 2] = fmaf(w.z, hB, aB[4 * tt + 2]);
                aA[4 * tt + 3] = fmaf(w.w, hA, aA[4 * tt + 3]);
                aB[4 * tt + 3] = fmaf(w.w, hB, aB[4 * tt + 3]);
            }
        }
    }
    // h2 = relu(acc) in place; pads stay 0
#pragma unroll
    for (int k = 0; k < 10; k++) {
        aA[k] = fmaxf(aA[k], 0.0f);
        aB[k] = fmaxf(aB[k], 0.0f);
    }
    aA[10] = 0.0f; aA[11] = 0.0f;
    aB[10] = 0.0f; aB[11] = 0.0f;
#pragma unroll
    for (int o = 0; o < OUT; o++) {
        float4 bq = c_w.b3v[M][o >> 2];
        float b = (o & 3) == 0 ? bq.x : (o & 3) == 1 ? bq.y
                : (o & 3) == 2 ? bq.z : bq.w;
        float sA = b, sB = b;
#pragma unroll
        for (int q = 0; q < 3; q++) {
            float4 v = c_w.w3[M][o][q];
            sA = fmaf(v.x, aA[4 * q + 0], sA);
            sB = fmaf(v.x, aB[4 * q + 0], sB);
            sA = fmaf(v.y, aA[4 * q + 1], sA);
            sB = fmaf(v.y, aB[4 * q + 1], sB);
            sA = fmaf(v.z, aA[4 * q + 2], sA);
            sB = fmaf(v.z, aB[4 * q + 2], sB);
            sA = fmaf(v.w, aA[4 * q + 3], sA);
            sB = fmaf(v.w, aB[4 * q + 3], sB);
        }
        outA[o] = sA;
        outB[o] = sB;
    }
}

__device__ __forceinline__ float softplus_f(float x)
{
    return fmaxf(x, 0.0f) + __logf(1.0f + __expf(-fabsf(x)));
}

__device__ __forceinline__ float sample_term(
    const float4 z, const float* mu, const float* off,
    float d0, float d1, float d2, float d3, float yx100, float yy100)
{
    float xi0 = fmaf(d0, z.x, mu[0]);
    float xi1 = fmaf(d1, z.y, fmaf(off[0], z.x, mu[1]));
    float xi2 = fmaf(d2, z.z, fmaf(off[2], z.y, fmaf(off[1], z.x, mu[2])));
    float xi3 = fmaf(d3, z.w, fmaf(off[5], z.z,
                  fmaf(off[4], z.y, fmaf(off[3], z.x, mu[3]))));

    float a2 = xi1 + xi2;
    float a3 = a2 + xi3;
    float s1, c1, s2, c2, s3, c3;
    __sincosf(xi1, &s1, &c1);
    __sincosf(a2,  &s2, &c2);
    __sincosf(a3,  &s3, &c3);

    float px = fmaf(0.5f, c1, fmaf(0.5f, c2, c3));
    float py = xi0 + fmaf(0.5f, s1, fmaf(0.5f, s2, s3));

    float rx = fmaf(-100.0f, px, yx100);
    float ry = fmaf(-100.0f, py, yy100);

    float s123 = fmaf(xi1, xi1, fmaf(xi2, xi2, xi3 * xi3));
    float t = fmaf(xi0 * -8.0f, xi0, -2.0f * s123);
    float r2 = fmaf(rx, rx, ry * ry);
    return fmaf(-0.5f, r2, t);
}

// ---------------------------------------------------------------------------
// 64-reg budget -> 4 blocks/SM -> 8 warps/SMSP.
__global__ void __launch_bounds__(NTHREADS, 4)
vi_kernel(const float* __restrict__ y, const float* __restrict__ zs, int N,
          float* __restrict__ out)
{
    __shared__ double sred[NTHREADS];
    __shared__ float wsum[NTHREADS / 32];
    __shared__ int sh_last;

    int tid = threadIdx.x;
    int g = blockIdx.x * NTHREADS + tid;
    int n0 = 2 * g, n1 = n0 + 1;
    float val = 0.0f;

    if (n0 < N) {
        bool two = (n1 < N);
        float4 yv;
        if (two) {
            yv = ((const float4*)y)[g];
        } else {
            float2 ya = ((const float2*)y)[n0];
            yv = make_float4(ya.x, ya.y, ya.x, ya.y);
            n1 = n0;
        }

        const float4* zpA = (const float4*)zs + (size_t)n0 * 8;
        const float4* zpB = (const float4*)zs + (size_t)n1 * 8;
        float4 zA = zpA[0];          // prefetch; hides under MLP block
        float4 zB = zpB[0];

        float muA[4], muB[4], ldA[4], ldB[4], ofA[6], ofB[6];
        mlp_eval2r<0, 4>(yv.x, yv.y, yv.z, yv.w, muA, muB);
        mlp_eval2r<1, 4>(yv.x, yv.y, yv.z, yv.w, ldA, ldB);
        mlp_eval2r<2, 6>(yv.x, yv.y, yv.z, yv.w, ofA, ofB);

        float d0A = softplus_f(ldA[0]), d0B = softplus_f(ldB[0]);
        float d1A = softplus_f(ldA[1]), d1B = softplus_f(ldB[1]);
        float d2A = softplus_f(ldA[2]), d2B = softplus_f(ldB[2]);
        float d3A = softplus_f(ldA[3]), d3B = softplus_f(ldB[3]);

        float yxA = yv.x * 100.0f, yyA = yv.y * 100.0f;
        float yxB = yv.z * 100.0f, yyB = yv.w * 100.0f;

        float accA = 0.0f, accB = 0.0f;
#pragma unroll
        for (int p = 0; p < 8; p++) {
            float4 za = zA, zb = zB;
            if (p < 7) { zA = zpA[p + 1]; zB = zpB[p + 1]; }
            accA += sample_term(za, muA, ofA, d0A, d1A, d2A, d3A, yxA, yyA);
            accB += sample_term(zb, muB, ofB, d0B, d1B, d2B, d3B, yxB, yyB);
        }

        float vA = fmaf(accA, 0.125f, C_PER_SAMPLE) + C_ENTROPY +
                   __logf(d0A * d1A * d2A * d3A);
        float vB = fmaf(accB, 0.125f, C_PER_SAMPLE) + C_ENTROPY +
                   __logf(d0B * d1B * d2B * d3B);
        val = two ? (vA + vB) : vA;
    }

    // ---- deterministic block reduction ----
#pragma unroll
    for (int o = 16; o > 0; o >>= 1)
        val += __shfl_down_sync(0xffffffffu, val, o);
    if ((tid & 31) == 0) wsum[tid >> 5] = val;
    __syncthreads();
    if (tid == 0) {
        double s = 0.0;
#pragma unroll
        for (int w = 0; w < NTHREADS / 32; w++) s += (double)wsum[w];
        g_partial[blockIdx.x] = s;
        __threadfence();
        unsigned t = atomicAdd(&g_ticket, 1u);
        sh_last = (t == gridDim.x - 1) ? 1 : 0;
    }
    __syncthreads();

    // ---- fused finalize: last block reduces partials deterministically ----
    if (sh_last) {
        __threadfence();
        double s = 0.0;
        for (int i = tid; i < (int)gridDim.x; i += NTHREADS)
            s += __ldcg(&g_partial[i]);
        sred[tid] = s;
        __syncthreads();
#pragma unroll
        for (int st = NTHREADS / 2; st > 0; st >>= 1) {
            if (tid < st) sred[tid] += sred[tid + st];
            __syncthreads();
        }
        if (tid == 0) {
            out[0] = (float)(sred[0] / (double)N);
            __threadfence();
            g_ticket = 0;   // reset for next graph replay
        }
    }
}

// ---------------------------------------------------------------------------
extern "C" void kernel_launch(void* const* d_in, const int* in_sizes, int n_in,
                              void* d_out, int out_size)
{
    const float* y  = (const float*)d_in[0];
    const float* zs = (const float*)d_in[1];
    int N = in_sizes[0] / 2;
    int npairs = (N + 1) / 2;
    int nblocks = (npairs + NTHREADS - 1) / NTHREADS;
    if (nblocks > MAX_BLOCKS) nblocks = MAX_BLOCKS;

    pack_kernel<<<1, 128>>>(
        (const float*)d_in[2],  (const float*)d_in[3],  (const float*)d_in[4],
        (const float*)d_in[5],  (const float*)d_in[6],  (const float*)d_in[7],
        (const float*)d_in[8],  (const float*)d_in[9],  (const float*)d_in[10],
        (const float*)d_in[11], (const float*)d_in[12], (const float*)d_in[13],
        (const float*)d_in[14], (const float*)d_in[15], (const float*)d_in[16],
        (const float*)d_in[17], (const float*)d_in[18], (const float*)d_in[19]);

    void* caddr = nullptr;
    void* saddr = nullptr;
    cudaGetSymbolAddress(&caddr, c_w);
    cudaGetSymbolAddress(&saddr, g_stage);
    cudaMemcpyAsync(caddr, saddr, sizeof(WPack), cudaMemcpyDeviceToDevice, 0);

    vi_kernel<<<nblocks, NTHREADS>>>(y, zs, N, (float*)d_out);
}